// round 4
// baseline (speedup 1.0000x reference)
#include <cuda_runtime.h>
#include <cstdint>

#define S_LEN 4096
#define BATCH 4
#define DIM 128
#define ROWS_TOTAL (BATCH * S_LEN)   // 16384
#define QKV_LD 384

// Scratch (no allocation allowed -> __device__ globals)
__device__ float g_qkv[ROWS_TOTAL * QKV_LD];    // 25.2 MB  [row][384] = q|k|v
__device__ float g_attn[ROWS_TOTAL * DIM];      // 8.4 MB
__device__ float g_rowmax[ROWS_TOTAL];
__device__ float g_rowinvz[ROWS_TOTAL];

// ---------------------------------------------------------------------------
// Fast exp for x <= 0. Degree-6 poly of 2^f + exponent splice. rel err ~2e-5.
// Avoids the MUFU.EX2 throughput wall (rt_SMSP=8).
// ---------------------------------------------------------------------------
__device__ __forceinline__ float fast_exp_neg(float x) {
    x = fmaxf(x, -87.0f);
    float t = x * 1.4426950408889634f;   // log2(e)
    float fi = floorf(t);
    float f = t - fi;
    float p = 1.5403530393381606e-4f;
    p = fmaf(p, f, 1.3333558146428443e-3f);
    p = fmaf(p, f, 9.6181291076284772e-3f);
    p = fmaf(p, f, 5.5504108664821580e-2f);
    p = fmaf(p, f, 2.4022650695910072e-1f);
    p = fmaf(p, f, 6.9314718055994531e-1f);
    p = fmaf(p, f, 1.0f);
    int i = (int)fi;                      // fi in [-126, 0]
    float s = __int_as_float((i + 127) << 23);
    return p * s;
}

__device__ __forceinline__ void ffma2(unsigned long long &acc,
                                      unsigned long long a,
                                      unsigned long long b) {
    asm("fma.rn.f32x2 %0, %1, %2, %0;" : "+l"(acc) : "l"(a), "l"(b));
}

__device__ __forceinline__ float pairsum(unsigned long long v) {
    float2 f = *reinterpret_cast<float2 *>(&v);
    return f.x + f.y;
}

// ---------------------------------------------------------------------------
// C[M,N] = A[M,128] @ B[N,128]^T (+bias) (optional band mask -> -1e30)
// K chunked at KC=32 with STATIC smem (34.8 KB) and register double-buffering.
// 128x128 block tile, 8x8 micro-tile per thread, f32x2 accumulation paired
// over k parity (operand pairs are k-contiguous natural LDS.64).
// ---------------------------------------------------------------------------
#define KC 32
#define ASTR 34   // smem row stride (floats): even (8B align); 17-in-8B-units
                  // stride mod 32 is odd -> conflict-free LDS.64

__global__ __launch_bounds__(256) void gemm_nt128(
    const float *__restrict__ A, const float *__restrict__ B,
    const float *__restrict__ bias, float *__restrict__ C,
    int lda, int ldb, int ldc,
    long long sA, long long sB, long long sC, int mask)
{
    __shared__ __align__(16) float As[128 * ASTR];
    __shared__ __align__(16) float Bs[128 * ASTR];

    const int bz = blockIdx.z;
    const int gi0 = blockIdx.y * 128;
    const int gj0 = blockIdx.x * 128;
    const float *Ab = A + (long long)bz * sA + (long long)gi0 * lda;
    const float *Bb = B + (long long)bz * sB + (long long)gj0 * ldb;

    const int tid = threadIdx.x;
    const int tx = tid & 15;
    const int ty = tid >> 4;

    // chunk-load mapping: 128 rows x 32 cols = 1024 float4; 4 per thread
    const int lrow[4] = { (tid + 0) >> 3, (tid + 256) >> 3,
                          (tid + 512) >> 3, (tid + 768) >> 3 };
    const int lcol = (tid & 7) * 4;

    unsigned long long acc[8][8];
#pragma unroll
    for (int i = 0; i < 8; ++i)
#pragma unroll
        for (int j = 0; j < 8; ++j) acc[i][j] = 0ULL;

    float4 ra[4], rb[4];
#pragma unroll
    for (int it = 0; it < 4; ++it) {
        ra[it] = *(const float4 *)&Ab[(long long)lrow[it] * lda + lcol];
        rb[it] = *(const float4 *)&Bb[(long long)lrow[it] * ldb + lcol];
    }

#pragma unroll
    for (int kc = 0; kc < 4; ++kc) {
        __syncthreads();   // previous chunk's compute done before overwrite
#pragma unroll
        for (int it = 0; it < 4; ++it) {
            float2 *da = (float2 *)&As[lrow[it] * ASTR + lcol];
            da[0] = make_float2(ra[it].x, ra[it].y);
            da[1] = make_float2(ra[it].z, ra[it].w);
            float2 *db = (float2 *)&Bs[lrow[it] * ASTR + lcol];
            db[0] = make_float2(rb[it].x, rb[it].y);
            db[1] = make_float2(rb[it].z, rb[it].w);
        }
        __syncthreads();

        if (kc < 3) {
            int ko = (kc + 1) * KC;
#pragma unroll
            for (int it = 0; it < 4; ++it) {
                ra[it] = *(const float4 *)&Ab[(long long)lrow[it] * lda + ko + lcol];
                rb[it] = *(const float4 *)&Bb[(long long)lrow[it] * ldb + ko + lcol];
            }
        }

#pragma unroll
        for (int kp = 0; kp < 16; ++kp) {
            unsigned long long ar[8], br[8];
#pragma unroll
            for (int ii = 0; ii < 8; ++ii)
                ar[ii] = *(const unsigned long long *)&As[(ty + ii * 16) * ASTR + kp * 2];
#pragma unroll
            for (int jj = 0; jj < 8; ++jj)
                br[jj] = *(const unsigned long long *)&Bs[(tx + jj * 16) * ASTR + kp * 2];
#pragma unroll
            for (int ii = 0; ii < 8; ++ii)
#pragma unroll
                for (int jj = 0; jj < 8; ++jj) ffma2(acc[ii][jj], ar[ii], br[jj]);
        }
    }

    // ---- epilogue ----
#pragma unroll
    for (int ii = 0; ii < 8; ++ii) {
        int row = gi0 + ty + ii * 16;
        float *Crow = C + (long long)bz * sC + (long long)row * ldc;
#pragma unroll
        for (int jj = 0; jj < 8; ++jj) {
            int col = gj0 + tx + jj * 16;
            float r = pairsum(acc[ii][jj]);
            if (bias) r += bias[col];
            if (mask) {
                int d = row - col;
                if (d <= 1 && d >= -1) r = -1.0e30f;
            }
            Crow[col] = r;
        }
    }
}

// ---------------------------------------------------------------------------
// Per-row max and 1/sum(exp). One block per row; 16 values/thread in regs.
// ---------------------------------------------------------------------------
__global__ __launch_bounds__(256) void rowstats_kernel(
    const float *__restrict__ Sc, float *__restrict__ M, float *__restrict__ Z)
{
    long long row = blockIdx.x;
    const float *p = Sc + row * (long long)S_LEN;
    int tid = threadIdx.x;

    float4 v[4];
#pragma unroll
    for (int q = 0; q < 4; ++q) v[q] = *(const float4 *)&p[(tid + q * 256) * 4];

    float mx = -3.0e38f;
#pragma unroll
    for (int q = 0; q < 4; ++q)
        mx = fmaxf(mx, fmaxf(fmaxf(v[q].x, v[q].y), fmaxf(v[q].z, v[q].w)));
#pragma unroll
    for (int o = 16; o; o >>= 1) mx = fmaxf(mx, __shfl_xor_sync(0xffffffffu, mx, o));

    __shared__ float red[8];
    if ((tid & 31) == 0) red[tid >> 5] = mx;
    __syncthreads();
    float m = red[0];
#pragma unroll
    for (int w = 1; w < 8; ++w) m = fmaxf(m, red[w]);
    __syncthreads();

    float sum = 0.0f;
#pragma unroll
    for (int q = 0; q < 4; ++q) {
        sum += fast_exp_neg(v[q].x - m);
        sum += fast_exp_neg(v[q].y - m);
        sum += fast_exp_neg(v[q].z - m);
        sum += fast_exp_neg(v[q].w - m);
    }
#pragma unroll
    for (int o = 16; o; o >>= 1) sum += __shfl_xor_sync(0xffffffffu, sum, o);
    if ((tid & 31) == 0) red[tid >> 5] = sum;
    __syncthreads();
    if (tid == 0) {
        float z = 0.0f;
#pragma unroll
        for (int w = 0; w < 8; ++w) z += red[w];
        M[row] = m;
        Z[row] = 1.0f / z;
    }
}

// ---------------------------------------------------------------------------
// PV: read raw scores from d_out weights region, convert to softmax weights
// (write back in place), and accumulate attn = W @ V with the f32x2
// micro-kernel. One block = 128 rows x all 128 d-cols; j streams in chunks of
// 16 with register-prefetch double buffering.
// ---------------------------------------------------------------------------
#define PSTR 20

__device__ __forceinline__ float wconv(float s, float m, float iz) {
    return (s > -1.0e29f) ? fast_exp_neg(s - m) * iz : 0.0f;
}

__global__ __launch_bounds__(256) void pv_kernel(
    float *__restrict__ Wts, const float *__restrict__ QKV,
    const float *__restrict__ rowmax, const float *__restrict__ rowinvz,
    float *__restrict__ attn)
{
    __shared__ __align__(16) float Ws[128 * PSTR];
    __shared__ __align__(16) float Vs[128 * PSTR];

    const int b = blockIdx.y;
    const int i0 = blockIdx.x * 128;
    const long long rowbase = (long long)b * S_LEN + i0;
    float *Wb = Wts + rowbase * S_LEN;
    const float *Vb = QKV + ((long long)b * S_LEN) * QKV_LD + 256;

    const int tid = threadIdx.x;
    const int tx = tid & 15;
    const int ty = tid >> 4;

    // score-tile mapping: 128 rows x 16 cols per chunk, 2 rows/thread
    const int arow0 = tid >> 2;          // 0..63 (and +64)
    const int ajq = (tid & 3) * 4;
    const float m0 = rowmax[rowbase + arow0];
    const float z0 = rowinvz[rowbase + arow0];
    const float m1 = rowmax[rowbase + arow0 + 64];
    const float z1 = rowinvz[rowbase + arow0 + 64];

    // V-tile mapping (stored transposed to smem): 16 j x 128 d per chunk
    const int vj = tid & 15;
    const int vdq = tid >> 4;            // 0..15 (and +16)

    unsigned long long acc[8][8];
#pragma unroll
    for (int i = 0; i < 8; ++i)
#pragma unroll
        for (int j = 0; j < 8; ++j) acc[i][j] = 0ULL;

    float4 pa0 = *(const float4 *)&Wb[(long long)arow0 * S_LEN + ajq];
    float4 pa1 = *(const float4 *)&Wb[(long long)(arow0 + 64) * S_LEN + ajq];
    float4 pv0 = *(const float4 *)&Vb[(long long)vj * QKV_LD + vdq * 4];
    float4 pv1 = *(const float4 *)&Vb[(long long)vj * QKV_LD + (vdq + 16) * 4];

    for (int jc = 0; jc < S_LEN; jc += 16) {
        // convert current chunk, stage to smem, write weights back to global
        float4 w0, w1;
        w0.x = wconv(pa0.x, m0, z0); w0.y = wconv(pa0.y, m0, z0);
        w0.z = wconv(pa0.z, m0, z0); w0.w = wconv(pa0.w, m0, z0);
        w1.x = wconv(pa1.x, m1, z1); w1.y = wconv(pa1.y, m1, z1);
        w1.z = wconv(pa1.z, m1, z1); w1.w = wconv(pa1.w, m1, z1);
        *(float4 *)&Ws[arow0 * PSTR + ajq] = w0;
        *(float4 *)&Ws[(arow0 + 64) * PSTR + ajq] = w1;
        *(float4 *)&Wb[(long long)arow0 * S_LEN + jc + ajq] = w0;
        *(float4 *)&Wb[(long long)(arow0 + 64) * S_LEN + jc + ajq] = w1;

        Vs[(vdq * 4 + 0) * PSTR + vj] = pv0.x;
        Vs[(vdq * 4 + 1) * PSTR + vj] = pv0.y;
        Vs[(vdq * 4 + 2) * PSTR + vj] = pv0.z;
        Vs[(vdq * 4 + 3) * PSTR + vj] = pv0.w;
        Vs[((vdq + 16) * 4 + 0) * PSTR + vj] = pv1.x;
        Vs[((vdq + 16) * 4 + 1) * PSTR + vj] = pv1.y;
        Vs[((vdq + 16) * 4 + 2) * PSTR + vj] = pv1.z;
        Vs[((vdq + 16) * 4 + 3) * PSTR + vj] = pv1.w;
        __syncthreads();

        // prefetch next chunk while computing this one
        if (jc + 16 < S_LEN) {
            pa0 = *(const float4 *)&Wb[(long long)arow0 * S_LEN + jc + 16 + ajq];
            pa1 = *(const float4 *)&Wb[(long long)(arow0 + 64) * S_LEN + jc + 16 + ajq];
            pv0 = *(const float4 *)&Vb[(long long)(jc + 16 + vj) * QKV_LD + vdq * 4];
            pv1 = *(const float4 *)&Vb[(long long)(jc + 16 + vj) * QKV_LD + (vdq + 16) * 4];
        }

#pragma unroll
        for (int kp = 0; kp < 8; ++kp) {
            unsigned long long ar[8], br[8];
#pragma unroll
            for (int ii = 0; ii < 8; ++ii)
                ar[ii] = *(const unsigned long long *)&Ws[(ty + ii * 16) * PSTR + kp * 2];
#pragma unroll
            for (int jj = 0; jj < 8; ++jj)
                br[jj] = *(const unsigned long long *)&Vs[(tx + jj * 16) * PSTR + kp * 2];
#pragma unroll
            for (int ii = 0; ii < 8; ++ii)
#pragma unroll
                for (int jj = 0; jj < 8; ++jj) ffma2(acc[ii][jj], ar[ii], br[jj]);
        }
        __syncthreads();
    }

#pragma unroll
    for (int ii = 0; ii < 8; ++ii) {
        long long row = rowbase + ty + ii * 16;
        float *Arow = attn + row * DIM;
#pragma unroll
        for (int jj = 0; jj < 8; ++jj)
            Arow[tx + jj * 16] = pairsum(acc[ii][jj]);
    }
}

// ---------------------------------------------------------------------------
// Host launcher
// ---------------------------------------------------------------------------
extern "C" void kernel_launch(void *const *d_in, const int *in_sizes, int n_in,
                              void *d_out, int out_size)
{
    const float *x    = (const float *)d_in[0];
    const float *Wqkv = (const float *)d_in[1];
    const float *bqkv = (const float *)d_in[2];
    const float *Wo   = (const float *)d_in[3];
    const float *bo   = (const float *)d_in[4];

    float *out   = (float *)d_out;
    float *out_y = out;                                   // [B,S,128]
    float *out_w = out + (size_t)ROWS_TOTAL * DIM;        // [B,1,S,S]

    float *qkv, *attn, *rm, *rz;
    cudaGetSymbolAddress((void **)&qkv, g_qkv);
    cudaGetSymbolAddress((void **)&attn, g_attn);
    cudaGetSymbolAddress((void **)&rm, g_rowmax);
    cudaGetSymbolAddress((void **)&rz, g_rowinvz);

    // K1: qkv = x @ Wqkv^T + bqkv    [16384, 384]
    gemm_nt128<<<dim3(3, 128, 1), 256>>>(
        x, Wqkv, bqkv, qkv, 128, 128, QKV_LD, 0, 0, 0, 0);

    // K2: raw masked scores -> weights region of d_out (legal scratch)
    gemm_nt128<<<dim3(32, 32, BATCH), 256>>>(
        qkv, qkv + 128, nullptr, out_w, QKV_LD, QKV_LD, S_LEN,
        (long long)S_LEN * QKV_LD, (long long)S_LEN * QKV_LD,
        (long long)S_LEN * S_LEN, 1);

    // K3: per-row max + 1/sumexp
    rowstats_kernel<<<ROWS_TOTAL, 256>>>(out_w, rm, rz);

    // K4: weights in-place into d_out + attn = W @ V
    pv_kernel<<<dim3(32, BATCH), 256>>>(out_w, qkv, rm, rz, attn);

    // K5: output = attn @ Wo^T + bo
    gemm_nt128<<<dim3(1, 128, 1), 256>>>(
        attn, Wo, bo, out_y, 128, 128, 128, 0, 0, 0, 0);
}

// round 5
// speedup vs baseline: 1.0685x; 1.0685x over previous
#include <cuda_runtime.h>
#include <cstdint>

#define S_LEN 4096
#define BATCH 4
#define DIM 128
#define ROWS_TOTAL (BATCH * S_LEN)   // 16384
#define QKV_LD 384

// Scratch (no allocation allowed -> __device__ globals)
__device__ float g_qkv[ROWS_TOTAL * QKV_LD];    // 25.2 MB  [row][384] = q|k|v
__device__ float g_vt[BATCH * DIM * S_LEN];     // 8.4 MB   V^T per batch [d][j]
__device__ float g_attn[ROWS_TOTAL * DIM];      // 8.4 MB
__device__ float g_rowmax[ROWS_TOTAL];
__device__ float g_rowinvz[ROWS_TOTAL];

// ---------------------------------------------------------------------------
// Fast exp for x <= 0. Degree-6 poly of 2^f + exponent splice. rel err ~2e-5.
// ---------------------------------------------------------------------------
__device__ __forceinline__ float fast_exp_neg(float x) {
    x = fmaxf(x, -87.0f);
    float t = x * 1.4426950408889634f;
    float fi = floorf(t);
    float f = t - fi;
    float p = 1.5403530393381606e-4f;
    p = fmaf(p, f, 1.3333558146428443e-3f);
    p = fmaf(p, f, 9.6181291076284772e-3f);
    p = fmaf(p, f, 5.5504108664821580e-2f);
    p = fmaf(p, f, 2.4022650695910072e-1f);
    p = fmaf(p, f, 6.9314718055994531e-1f);
    p = fmaf(p, f, 1.0f);
    int i = (int)fi;
    float s = __int_as_float((i + 127) << 23);
    return p * s;
}

__device__ __forceinline__ void ffma2(unsigned long long &acc,
                                      unsigned long long a,
                                      unsigned long long b) {
    asm("fma.rn.f32x2 %0, %1, %2, %0;" : "+l"(acc) : "l"(a), "l"(b));
}

__device__ __forceinline__ float pairsum(unsigned long long v) {
    float2 f = *reinterpret_cast<float2 *>(&v);
    return f.x + f.y;
}

// ---------------------------------------------------------------------------
// Unified GEMM: C[64,128] tile = A[64,128] @ B[128,128]^T (+bias, +band mask)
// K=128 in 4 chunks of 32; static smem 26KB; 128 threads; 8x8 micro-tile;
// f32x2 accumulation paired over k parity. 2 CTAs/SM.
// ---------------------------------------------------------------------------
#define KC 32
#define ASTR 34   // floats; 17 (odd) 8B-banks stride -> conflict-free LDS.64

__global__ __launch_bounds__(128, 2) void gemm64(
    const float *__restrict__ A, const float *__restrict__ B,
    const float *__restrict__ bias, float *__restrict__ C,
    int lda, int ldb, int ldc,
    long long sA, long long sB, long long sC, int mask)
{
    __shared__ __align__(16) float As[64 * ASTR];
    __shared__ __align__(16) float Bs[128 * ASTR];

    const int bz = blockIdx.z;
    const int gi0 = blockIdx.y * 64;
    const int gj0 = blockIdx.x * 128;
    const float *Ab = A + (long long)bz * sA + (long long)gi0 * lda;
    const float *Bb = B + (long long)bz * sB + (long long)gj0 * ldb;

    const int tid = threadIdx.x;
    const int tx = tid & 15;
    const int ty = tid >> 4;          // 0..7

    const int lcol = (tid & 7) * 4;
    int arow[4], brow[8];
#pragma unroll
    for (int it = 0; it < 4; ++it) arow[it] = (tid + 128 * it) >> 3;  // 0..63
#pragma unroll
    for (int it = 0; it < 8; ++it) brow[it] = (tid + 128 * it) >> 3;  // 0..127

    unsigned long long acc[8][8];
#pragma unroll
    for (int i = 0; i < 8; ++i)
#pragma unroll
        for (int j = 0; j < 8; ++j) acc[i][j] = 0ULL;

    float4 ra[4], rb[8];
#pragma unroll
    for (int it = 0; it < 4; ++it)
        ra[it] = *(const float4 *)&Ab[(long long)arow[it] * lda + lcol];
#pragma unroll
    for (int it = 0; it < 8; ++it)
        rb[it] = *(const float4 *)&Bb[(long long)brow[it] * ldb + lcol];

#pragma unroll
    for (int kc = 0; kc < 4; ++kc) {
        __syncthreads();
#pragma unroll
        for (int it = 0; it < 4; ++it) {
            float2 *d = (float2 *)&As[arow[it] * ASTR + lcol];
            d[0] = make_float2(ra[it].x, ra[it].y);
            d[1] = make_float2(ra[it].z, ra[it].w);
        }
#pragma unroll
        for (int it = 0; it < 8; ++it) {
            float2 *d = (float2 *)&Bs[brow[it] * ASTR + lcol];
            d[0] = make_float2(rb[it].x, rb[it].y);
            d[1] = make_float2(rb[it].z, rb[it].w);
        }
        __syncthreads();

        if (kc < 3) {
            int ko = (kc + 1) * KC;
#pragma unroll
            for (int it = 0; it < 4; ++it)
                ra[it] = *(const float4 *)&Ab[(long long)arow[it] * lda + ko + lcol];
#pragma unroll
            for (int it = 0; it < 8; ++it)
                rb[it] = *(const float4 *)&Bb[(long long)brow[it] * ldb + ko + lcol];
        }

#pragma unroll
        for (int kp = 0; kp < 16; ++kp) {
            unsigned long long ar[8], br[8];
#pragma unroll
            for (int ii = 0; ii < 8; ++ii)
                ar[ii] = *(const unsigned long long *)&As[(ty + ii * 8) * ASTR + kp * 2];
#pragma unroll
            for (int jj = 0; jj < 8; ++jj)
                br[jj] = *(const unsigned long long *)&Bs[(tx + jj * 16) * ASTR + kp * 2];
#pragma unroll
            for (int ii = 0; ii < 8; ++ii)
#pragma unroll
                for (int jj = 0; jj < 8; ++jj) ffma2(acc[ii][jj], ar[ii], br[jj]);
        }
    }

#pragma unroll
    for (int ii = 0; ii < 8; ++ii) {
        int row = gi0 + ty + ii * 8;
        float *Crow = C + (long long)bz * sC + (long long)row * ldc;
#pragma unroll
        for (int jj = 0; jj < 8; ++jj) {
            int col = gj0 + tx + jj * 16;
            float r = pairsum(acc[ii][jj]);
            if (bias) r += bias[col];
            if (mask) {
                int d = row - col;
                if (d <= 1 && d >= -1) r = -1.0e30f;
            }
            Crow[col] = r;
        }
    }
}

// ---------------------------------------------------------------------------
// V transpose: vt[b][d][j] = qkv[b][j][256+d]
// ---------------------------------------------------------------------------
__global__ void transpose_v(const float *__restrict__ qkv, float *__restrict__ vt)
{
    __shared__ float t[32][33];
    int b = blockIdx.z;
    int j0 = blockIdx.x * 32, d0 = blockIdx.y * 32;
    const float *base = qkv + (long long)b * S_LEN * QKV_LD;
#pragma unroll
    for (int r = threadIdx.y; r < 32; r += 8)
        t[r][threadIdx.x] = base[(long long)(j0 + r) * QKV_LD + 256 + d0 + threadIdx.x];
    __syncthreads();
    float *out = vt + ((long long)b * DIM + d0) * S_LEN + j0;
#pragma unroll
    for (int r = threadIdx.y; r < 32; r += 8)
        out[(long long)r * S_LEN + threadIdx.x] = t[threadIdx.x][r];
}

// ---------------------------------------------------------------------------
// Per-row max and 1/sum(exp). One block per row; 16 values/thread in regs.
// ---------------------------------------------------------------------------
__global__ __launch_bounds__(256) void rowstats_kernel(
    const float *__restrict__ Sc, float *__restrict__ M, float *__restrict__ Z)
{
    long long row = blockIdx.x;
    const float *p = Sc + row * (long long)S_LEN;
    int tid = threadIdx.x;

    float4 v[4];
#pragma unroll
    for (int q = 0; q < 4; ++q) v[q] = *(const float4 *)&p[(tid + q * 256) * 4];

    float mx = -3.0e38f;
#pragma unroll
    for (int q = 0; q < 4; ++q)
        mx = fmaxf(mx, fmaxf(fmaxf(v[q].x, v[q].y), fmaxf(v[q].z, v[q].w)));
#pragma unroll
    for (int o = 16; o; o >>= 1) mx = fmaxf(mx, __shfl_xor_sync(0xffffffffu, mx, o));

    __shared__ float red[8];
    if ((tid & 31) == 0) red[tid >> 5] = mx;
    __syncthreads();
    float m = red[0];
#pragma unroll
    for (int w = 1; w < 8; ++w) m = fmaxf(m, red[w]);
    __syncthreads();

    float sum = 0.0f;
#pragma unroll
    for (int q = 0; q < 4; ++q) {
        sum += fast_exp_neg(v[q].x - m);
        sum += fast_exp_neg(v[q].y - m);
        sum += fast_exp_neg(v[q].z - m);
        sum += fast_exp_neg(v[q].w - m);
    }
#pragma unroll
    for (int o = 16; o; o >>= 1) sum += __shfl_xor_sync(0xffffffffu, sum, o);
    if ((tid & 31) == 0) red[tid >> 5] = sum;
    __syncthreads();
    if (tid == 0) {
        float z = 0.0f;
#pragma unroll
        for (int w = 0; w < 8; ++w) z += red[w];
        M[row] = m;
        Z[row] = 1.0f / z;
    }
}

// ---------------------------------------------------------------------------
// PV: same 64x128/8x8 GEMM structure, K=4096 streamed in 32-wide chunks.
// A-tile loader converts raw scores -> weights (in place: writes converted
// float4 back to d_out) and stages to smem. B = V^T (ldb = S_LEN).
// Grid 256 CTAs -> single resident wave at 2 CTAs/SM.
// ---------------------------------------------------------------------------
__device__ __forceinline__ float4 wconv4(float4 s, float m, float iz) {
    float4 w;
    w.x = (s.x > -1.0e29f) ? fast_exp_neg(s.x - m) * iz : 0.0f;
    w.y = (s.y > -1.0e29f) ? fast_exp_neg(s.y - m) * iz : 0.0f;
    w.z = (s.z > -1.0e29f) ? fast_exp_neg(s.z - m) * iz : 0.0f;
    w.w = (s.w > -1.0e29f) ? fast_exp_neg(s.w - m) * iz : 0.0f;
    return w;
}

__global__ __launch_bounds__(128, 2) void pv64(
    float *__restrict__ Wts, const float *__restrict__ Vt,
    const float *__restrict__ rowmax, const float *__restrict__ rowinvz,
    float *__restrict__ attn)
{
    __shared__ __align__(16) float Ws[64 * ASTR];
    __shared__ __align__(16) float Vs[128 * ASTR];

    const int b = blockIdx.y;
    const int i0 = blockIdx.x * 64;
    const long long rowbase = (long long)b * S_LEN + i0;
    float *Wb = Wts + rowbase * S_LEN;
    const float *Vb = Vt + (long long)b * DIM * S_LEN;

    const int tid = threadIdx.x;
    const int tx = tid & 15;
    const int ty = tid >> 4;

    const int lcol = (tid & 7) * 4;
    int arow[4], brow[8];
    float am[4], az[4];
#pragma unroll
    for (int it = 0; it < 4; ++it) {
        arow[it] = (tid + 128 * it) >> 3;
        am[it] = rowmax[rowbase + arow[it]];
        az[it] = rowinvz[rowbase + arow[it]];
    }
#pragma unroll
    for (int it = 0; it < 8; ++it) brow[it] = (tid + 128 * it) >> 3;

    unsigned long long acc[8][8];
#pragma unroll
    for (int i = 0; i < 8; ++i)
#pragma unroll
        for (int j = 0; j < 8; ++j) acc[i][j] = 0ULL;

    float4 ra[4], rb[8];
#pragma unroll
    for (int it = 0; it < 4; ++it)
        ra[it] = *(const float4 *)&Wb[(long long)arow[it] * S_LEN + lcol];
#pragma unroll
    for (int it = 0; it < 8; ++it)
        rb[it] = *(const float4 *)&Vb[(long long)brow[it] * S_LEN + lcol];

    for (int jc = 0; jc < S_LEN; jc += KC) {
        __syncthreads();
#pragma unroll
        for (int it = 0; it < 4; ++it) {
            float4 w = wconv4(ra[it], am[it], az[it]);
            float2 *d = (float2 *)&Ws[arow[it] * ASTR + lcol];
            d[0] = make_float2(w.x, w.y);
            d[1] = make_float2(w.z, w.w);
            *(float4 *)&Wb[(long long)arow[it] * S_LEN + jc + lcol] = w;
        }
#pragma unroll
        for (int it = 0; it < 8; ++it) {
            float2 *d = (float2 *)&Vs[brow[it] * ASTR + lcol];
            d[0] = make_float2(rb[it].x, rb[it].y);
            d[1] = make_float2(rb[it].z, rb[it].w);
        }
        __syncthreads();

        if (jc + KC < S_LEN) {
            int ko = jc + KC;
#pragma unroll
            for (int it = 0; it < 4; ++it)
                ra[it] = *(const float4 *)&Wb[(long long)arow[it] * S_LEN + ko + lcol];
#pragma unroll
            for (int it = 0; it < 8; ++it)
                rb[it] = *(const float4 *)&Vb[(long long)brow[it] * S_LEN + ko + lcol];
        }

#pragma unroll
        for (int kp = 0; kp < 16; ++kp) {
            unsigned long long ar[8], br[8];
#pragma unroll
            for (int ii = 0; ii < 8; ++ii)
                ar[ii] = *(const unsigned long long *)&Ws[(ty + ii * 8) * ASTR + kp * 2];
#pragma unroll
            for (int jj = 0; jj < 8; ++jj)
                br[jj] = *(const unsigned long long *)&Vs[(tx + jj * 16) * ASTR + kp * 2];
#pragma unroll
            for (int ii = 0; ii < 8; ++ii)
#pragma unroll
                for (int jj = 0; jj < 8; ++jj) ffma2(acc[ii][jj], ar[ii], br[jj]);
        }
    }

#pragma unroll
    for (int ii = 0; ii < 8; ++ii) {
        long long row = rowbase + ty + ii * 8;
        float *Arow = attn + row * DIM;
#pragma unroll
        for (int jj = 0; jj < 8; ++jj)
            Arow[tx + jj * 16] = pairsum(acc[ii][jj]);
    }
}

// ---------------------------------------------------------------------------
// Host launcher
// ---------------------------------------------------------------------------
extern "C" void kernel_launch(void *const *d_in, const int *in_sizes, int n_in,
                              void *d_out, int out_size)
{
    const float *x    = (const float *)d_in[0];
    const float *Wqkv = (const float *)d_in[1];
    const float *bqkv = (const float *)d_in[2];
    const float *Wo   = (const float *)d_in[3];
    const float *bo   = (const float *)d_in[4];

    float *out   = (float *)d_out;
    float *out_y = out;                                   // [B,S,128]
    float *out_w = out + (size_t)ROWS_TOTAL * DIM;        // [B,1,S,S]

    float *qkv, *vt, *attn, *rm, *rz;
    cudaGetSymbolAddress((void **)&qkv, g_qkv);
    cudaGetSymbolAddress((void **)&vt, g_vt);
    cudaGetSymbolAddress((void **)&attn, g_attn);
    cudaGetSymbolAddress((void **)&rm, g_rowmax);
    cudaGetSymbolAddress((void **)&rz, g_rowinvz);

    // K1: qkv = x @ Wqkv^T + bqkv    [16384, 384]
    gemm64<<<dim3(3, 256, 1), 128>>>(
        x, Wqkv, bqkv, qkv, 128, 128, QKV_LD, 0, 0, 0, 0);

    // K1b: vt[b][d][j] = v[b][j][d]
    transpose_v<<<dim3(S_LEN / 32, DIM / 32, BATCH), dim3(32, 8)>>>(qkv, vt);

    // K2: raw masked scores -> weights region of d_out (legal scratch)
    gemm64<<<dim3(32, 64, BATCH), 128>>>(
        qkv, qkv + 128, nullptr, out_w, QKV_LD, QKV_LD, S_LEN,
        (long long)S_LEN * QKV_LD, (long long)S_LEN * QKV_LD,
        (long long)S_LEN * S_LEN, 1);

    // K3: per-row max + 1/sumexp
    rowstats_kernel<<<ROWS_TOTAL, 256>>>(out_w, rm, rz);

    // K4: weights in-place into d_out + attn = W @ V
    pv64<<<dim3(64, BATCH), 128>>>(out_w, vt, rm, rz, attn);

    // K5: output = attn @ Wo^T + bo
    gemm64<<<dim3(1, 256, 1), 128>>>(
        attn, Wo, bo, out_y, 128, 128, 128, 0, 0, 0, 0);
}